// round 1
// baseline (speedup 1.0000x reference)
#include <cuda_runtime.h>

// TopKMoE: T=4096 tokens, D=256, H=512, E=8, top-2.
// Pipeline: zero counts -> gate+compact -> FFN1 grouped GEMM (relu) -> FFN2
// grouped GEMM (+weighted atomic scatter into out). All fp32 SIMT this round.

#define T_TOKENS 4096
#define D_MODEL  256
#define H_DIM    512
#define N_EXP    8

#define BM 64
#define BN 64
#define BK 32

// Scratch (device globals; no runtime allocation allowed).
__device__ int   g_cnt[N_EXP];
__device__ int   g_tok[N_EXP * T_TOKENS];
__device__ float g_wt [N_EXP * T_TOKENS];
__device__ float g_h  [(size_t)N_EXP * T_TOKENS * H_DIM];   // 64 MB

__global__ void zero_cnt_kernel() {
    if (threadIdx.x < N_EXP) g_cnt[threadIdx.x] = 0;
}

// ---------------------------------------------------------------------------
// Gating: logits = x @ Wg + bg + bias; top-2 (tie -> lower index first, like
// jax.lax.top_k); softmax over the 2; append token to each expert's list.
// ---------------------------------------------------------------------------
__global__ __launch_bounds__(256)
void gate_kernel(const float* __restrict__ x,
                 const float* __restrict__ Wg,
                 const float* __restrict__ bg,
                 const float* __restrict__ bias) {
    __shared__ float sWg[D_MODEL * N_EXP];   // 8 KB
    for (int i = threadIdx.x; i < D_MODEL * N_EXP; i += blockDim.x)
        sWg[i] = Wg[i];
    __syncthreads();

    int t = blockIdx.x * blockDim.x + threadIdx.x;
    if (t >= T_TOKENS) return;

    const float* xr = x + (size_t)t * D_MODEL;
    float acc[N_EXP];
#pragma unroll
    for (int e = 0; e < N_EXP; e++) acc[e] = 0.f;

    for (int k = 0; k < D_MODEL; k++) {
        float xv = xr[k];
#pragma unroll
        for (int e = 0; e < N_EXP; e++)
            acc[e] += xv * sWg[k * N_EXP + e];
    }
#pragma unroll
    for (int e = 0; e < N_EXP; e++) acc[e] += bg[e] + bias[e];

    // top-2 with lowest-index-first tie-break
    float best = -3.402823466e+38f, sec = -3.402823466e+38f;
    int bi = -1, si = -1;
#pragma unroll
    for (int e = 0; e < N_EXP; e++) {
        float v = acc[e];
        if (v > best) { sec = best; si = bi; best = v; bi = e; }
        else if (v > sec) { sec = v; si = e; }
    }

    // stable softmax over {best, sec}
    float w1 = __expf(sec - best);      // exp(0)=1 for best
    float inv = 1.f / (1.f + w1);
    float w0 = inv;
    w1 *= inv;

    int p0 = atomicAdd(&g_cnt[bi], 1);
    g_tok[bi * T_TOKENS + p0] = t;
    g_wt [bi * T_TOKENS + p0] = w0;
    int p1 = atomicAdd(&g_cnt[si], 1);
    g_tok[si * T_TOKENS + p1] = t;
    g_wt [si * T_TOKENS + p1] = w1;
}

// ---------------------------------------------------------------------------
// Stage 1: h = relu(gather(x) @ W1[e] + b1[e])  -> g_h
// M = cnt(e) (gathered token rows), N = 512, K = 256.
// grid = (64 m-tiles, 8 n-tiles, 8 experts); early-exit past cnt.
// ---------------------------------------------------------------------------
__global__ __launch_bounds__(256)
void ffn1_kernel(const float* __restrict__ x,
                 const float* __restrict__ W1,
                 const float* __restrict__ b1) {
    int e   = blockIdx.z;
    int cnt = g_cnt[e];
    int m0  = blockIdx.x * BM;
    if (m0 >= cnt) return;
    int n0  = blockIdx.y * BN;

    __shared__ float As[BK][BM + 1];   // transposed A tile, padded
    __shared__ float Bs[BK][BN];
    __shared__ int   toks[BM];

    int t = threadIdx.x;
    if (t < BM) {
        int m = m0 + t;
        toks[t] = (m < cnt) ? g_tok[e * T_TOKENS + m] : -1;
    }
    __syncthreads();

    const float* Wb = W1 + (size_t)e * D_MODEL * H_DIM;
    int ty = t >> 4, tx = t & 15;      // 16x16 thread grid, 4x4 microtile
    float acc[4][4];
#pragma unroll
    for (int i = 0; i < 4; i++)
#pragma unroll
        for (int j = 0; j < 4; j++) acc[i][j] = 0.f;

    for (int k0 = 0; k0 < D_MODEL; k0 += BK) {
        // A tile: 64 rows x 32 k, gathered, stored transposed
#pragma unroll
        for (int i = 0; i < 8; i++) {
            int row = (t >> 5) + i * 8;
            int col = t & 31;
            int tok = toks[row];
            As[col][row] = (tok >= 0) ? x[(size_t)tok * D_MODEL + k0 + col] : 0.f;
        }
        // B tile: 32 k x 64 n (float4)
#pragma unroll
        for (int i = 0; i < 2; i++) {
            int row  = (t >> 4) + i * 16;
            int colv = t & 15;
            float4 v = *(const float4*)(Wb + (size_t)(k0 + row) * H_DIM + n0 + colv * 4);
            *(float4*)&Bs[row][colv * 4] = v;
        }
        __syncthreads();

#pragma unroll 8
        for (int k = 0; k < BK; k++) {
            float a[4], b[4];
#pragma unroll
            for (int i = 0; i < 4; i++) a[i] = As[k][ty * 4 + i];
#pragma unroll
            for (int j = 0; j < 4; j++) b[j] = Bs[k][tx * 4 + j];
#pragma unroll
            for (int i = 0; i < 4; i++)
#pragma unroll
                for (int j = 0; j < 4; j++)
                    acc[i][j] += a[i] * b[j];
        }
        __syncthreads();
    }

    // epilogue: + b1, relu, store
#pragma unroll
    for (int i = 0; i < 4; i++) {
        int m = m0 + ty * 4 + i;
        if (m >= cnt) continue;
        float* hrow = g_h + ((size_t)e * T_TOKENS + m) * H_DIM;
#pragma unroll
        for (int j = 0; j < 4; j++) {
            int n = n0 + tx * 4 + j;
            float v = acc[i][j] + b1[e * H_DIM + n];
            hrow[n] = fmaxf(v, 0.f);
        }
    }
}

// ---------------------------------------------------------------------------
// Stage 2: y = h @ W2[e] + b2[e];  out[tok] += w * y   (atomic scatter)
// M = cnt(e), N = 256, K = 512.  grid = (64, 4, 8).
// ---------------------------------------------------------------------------
__global__ __launch_bounds__(256)
void ffn2_kernel(const float* __restrict__ W2,
                 const float* __restrict__ b2,
                 float* __restrict__ out) {
    int e   = blockIdx.z;
    int cnt = g_cnt[e];
    int m0  = blockIdx.x * BM;
    if (m0 >= cnt) return;
    int n0  = blockIdx.y * BN;

    __shared__ float As[BK][BM + 1];
    __shared__ float Bs[BK][BN];

    int t = threadIdx.x;
    const float* Wb = W2 + (size_t)e * H_DIM * D_MODEL;
    const float* hb = g_h + (size_t)e * T_TOKENS * H_DIM;

    int ty = t >> 4, tx = t & 15;
    float acc[4][4];
#pragma unroll
    for (int i = 0; i < 4; i++)
#pragma unroll
        for (int j = 0; j < 4; j++) acc[i][j] = 0.f;

    for (int k0 = 0; k0 < H_DIM; k0 += BK) {
        // A tile: rows are contiguous in g_h (stale rows past cnt are finite junk)
#pragma unroll
        for (int i = 0; i < 8; i++) {
            int row = (t >> 5) + i * 8;
            int col = t & 31;
            As[col][row] = hb[(size_t)(m0 + row) * H_DIM + k0 + col];
        }
#pragma unroll
        for (int i = 0; i < 2; i++) {
            int row  = (t >> 4) + i * 16;
            int colv = t & 15;
            float4 v = *(const float4*)(Wb + (size_t)(k0 + row) * D_MODEL + n0 + colv * 4);
            *(float4*)&Bs[row][colv * 4] = v;
        }
        __syncthreads();

#pragma unroll 8
        for (int k = 0; k < BK; k++) {
            float a[4], b[4];
#pragma unroll
            for (int i = 0; i < 4; i++) a[i] = As[k][ty * 4 + i];
#pragma unroll
            for (int j = 0; j < 4; j++) b[j] = Bs[k][tx * 4 + j];
#pragma unroll
            for (int i = 0; i < 4; i++)
#pragma unroll
                for (int j = 0; j < 4; j++)
                    acc[i][j] += a[i] * b[j];
        }
        __syncthreads();
    }

#pragma unroll
    for (int i = 0; i < 4; i++) {
        int m = m0 + ty * 4 + i;
        if (m >= cnt) continue;
        int   tok = g_tok[e * T_TOKENS + m];
        float w   = g_wt [e * T_TOKENS + m];
        float* orow = out + (size_t)tok * D_MODEL;
#pragma unroll
        for (int j = 0; j < 4; j++) {
            int n = n0 + tx * 4 + j;
            atomicAdd(&orow[n], w * (acc[i][j] + b2[e * D_MODEL + n]));
        }
    }
}

// ---------------------------------------------------------------------------
extern "C" void kernel_launch(void* const* d_in, const int* in_sizes, int n_in,
                              void* d_out, int out_size) {
    const float* x    = (const float*)d_in[0];
    const float* Wg   = (const float*)d_in[1];
    const float* bg   = (const float*)d_in[2];
    const float* bias = (const float*)d_in[3];
    const float* W1   = (const float*)d_in[4];
    const float* b1   = (const float*)d_in[5];
    const float* W2   = (const float*)d_in[6];
    const float* b2   = (const float*)d_in[7];
    float* out = (float*)d_out;

    cudaMemsetAsync(out, 0, (size_t)out_size * sizeof(float));
    zero_cnt_kernel<<<1, 32>>>();
    gate_kernel<<<(T_TOKENS + 255) / 256, 256>>>(x, Wg, bg, bias);

    dim3 g1(T_TOKENS / BM, H_DIM / BN, N_EXP);   // (64, 8, 8)
    ffn1_kernel<<<g1, 256>>>(x, W1, b1);

    dim3 g2(T_TOKENS / BM, D_MODEL / BN, N_EXP); // (64, 4, 8)
    ffn2_kernel<<<g2, 256>>>(W2, b2, out);
}

// round 12
// speedup vs baseline: 2.8818x; 2.8818x over previous
#include <cuda_runtime.h>
#include <cstdint>

// TopKMoE on GB300 via legacy mma.sync tf32 (compute_103-safe; no tcgen05).
// gate -> compact -> FFN1 grouped GEMM (relu) -> FFN2 grouped GEMM -> combine.
// T=4096 tokens, D=256, H=512, E=8, top-2.

#define T_TOKENS 4096
#define D_MODEL  256
#define H_DIM    512
#define N_EXP    8

// ---------------- device scratch (no runtime allocation allowed) ------------
__device__ int   g_cnt[N_EXP];
__device__ int   g_tok[N_EXP * T_TOKENS];
__device__ int   g_a0[T_TOKENS];          // e*T + slot for top-1
__device__ int   g_a1[T_TOKENS];          // e*T + slot for top-2
__device__ float g_wa[T_TOKENS];
__device__ float g_wb[T_TOKENS];
__device__ float g_xt [T_TOKENS * D_MODEL];                  // x tf32-rounded
__device__ float g_w1t[N_EXP * D_MODEL * H_DIM];             // W1 tf32 [e][k][n]
__device__ float g_w2t[N_EXP * H_DIM * D_MODEL];             // W2 tf32 [e][k][n]
__device__ float g_h  [(size_t)N_EXP * T_TOKENS * H_DIM];    // FFN1 out (tf32)
__device__ float g_y  [(size_t)N_EXP * T_TOKENS * D_MODEL];  // FFN2 out (fp32)

// ---------------- helpers ----------------------------------------------------
__device__ __forceinline__ uint32_t smem_u32(const void* p) {
    uint32_t a;
    asm("{ .reg .u64 t; cvta.to.shared.u64 t, %1; cvt.u32.u64 %0, t; }" : "=r"(a) : "l"(p));
    return a;
}
__device__ __forceinline__ float to_tf32(float f) {
    uint32_t u;
    asm("cvt.rna.tf32.f32 %0, %1;" : "=r"(u) : "f"(f));
    return __uint_as_float(u);
}
__device__ __forceinline__ void cp_async16(uint32_t dst, const void* src) {
    asm volatile("cp.async.cg.shared.global [%0], [%1], 16;"
                 :: "r"(dst), "l"(__cvta_generic_to_global(src)) : "memory");
}
#define CP_COMMIT() asm volatile("cp.async.commit_group;" ::: "memory")
#define CP_WAIT0()  asm volatile("cp.async.wait_group 0;" ::: "memory")
#define CP_WAIT1()  asm volatile("cp.async.wait_group 1;" ::: "memory")

__device__ __forceinline__ void mma_tf32(float4& d, const uint32_t a[4],
                                         uint32_t b0, uint32_t b1) {
    asm volatile("mma.sync.aligned.m16n8k8.row.col.f32.tf32.tf32.f32 "
                 "{%0,%1,%2,%3}, {%4,%5,%6,%7}, {%8,%9}, {%0,%1,%2,%3};"
                 : "+f"(d.x), "+f"(d.y), "+f"(d.z), "+f"(d.w)
                 : "r"(a[0]), "r"(a[1]), "r"(a[2]), "r"(a[3]), "r"(b0), "r"(b1));
}

// ---------------- prep: tf32-round x/W1/W2 (layouts unchanged), zero counts --
__global__ __launch_bounds__(256)
void prep_kernel(const float* __restrict__ x,
                 const float* __restrict__ W1,
                 const float* __restrict__ W2) {
    int idx = blockIdx.x * 256 + threadIdx.x;         // 786432 float4s
    if (blockIdx.x == 0 && threadIdx.x < N_EXP) g_cnt[threadIdx.x] = 0;
    const float4* src;
    float4* dst;
    int j;
    if (idx < 262144)       { src = (const float4*)x;  dst = (float4*)g_xt;  j = idx; }
    else if (idx < 524288)  { src = (const float4*)W1; dst = (float4*)g_w1t; j = idx - 262144; }
    else                    { src = (const float4*)W2; dst = (float4*)g_w2t; j = idx - 524288; }
    float4 v = src[j];
    v.x = to_tf32(v.x); v.y = to_tf32(v.y); v.z = to_tf32(v.z); v.w = to_tf32(v.w);
    dst[j] = v;
}

// ---------------- gate: warp per token ---------------------------------------
__global__ __launch_bounds__(256)
void gate_kernel(const float* __restrict__ x,
                 const float* __restrict__ Wg,
                 const float* __restrict__ bg,
                 const float* __restrict__ bias) {
    __shared__ float sWg[D_MODEL * N_EXP];
    __shared__ float sB[N_EXP];
    int t = threadIdx.x;
    for (int i = t; i < D_MODEL * N_EXP; i += 256) sWg[i] = Wg[i];
    if (t < N_EXP) sB[t] = bg[t] + bias[t];
    __syncthreads();

    int warp = t >> 5, lane = t & 31;
    int tok = blockIdx.x * 8 + warp;
    const float* xr = x + (size_t)tok * D_MODEL;
    float acc[N_EXP];
#pragma unroll
    for (int e = 0; e < N_EXP; e++) acc[e] = 0.f;
    for (int k = lane; k < D_MODEL; k += 32) {
        float xv = xr[k];
#pragma unroll
        for (int e = 0; e < N_EXP; e++) acc[e] += xv * sWg[k * N_EXP + e];
    }
#pragma unroll
    for (int e = 0; e < N_EXP; e++)
#pragma unroll
        for (int o = 16; o > 0; o >>= 1)
            acc[e] += __shfl_xor_sync(0xFFFFFFFF, acc[e], o);

    if (lane == 0) {
        float best = -3.402823466e+38f, sec = -3.402823466e+38f;
        int bi = -1, si = -1;
#pragma unroll
        for (int e = 0; e < N_EXP; e++) {
            float v = acc[e] + sB[e];
            if (v > best) { sec = best; si = bi; best = v; bi = e; }
            else if (v > sec) { sec = v; si = e; }
        }
        float w1 = __expf(sec - best);
        float inv = 1.f / (1.f + w1);
        float w0 = inv; w1 *= inv;
        int p0 = atomicAdd(&g_cnt[bi], 1);
        g_tok[bi * T_TOKENS + p0] = tok;
        int p1 = atomicAdd(&g_cnt[si], 1);
        g_tok[si * T_TOKENS + p1] = tok;
        g_a0[tok] = bi * T_TOKENS + p0;  g_wa[tok] = w0;
        g_a1[tok] = si * T_TOKENS + p1;  g_wb[tok] = w1;
    }
}

// ---------------- grouped tf32 GEMM via mma.sync ----------------------------
// CTA tile 128x128, BK=32. 8 warps as 4(M) x 2(N); warp tile 32x64.
// Smem strides chosen so every fragment LDS is conflict-free:
//   A row-stride 36 floats  -> addr%32 = 4g+tt (bijective over warp)
//   B row-stride 136 floats -> addr%32 = 8tt+g (bijective over warp)
#define TOK_OFF 0
#define A_OFF   128
#define A_FLTS  (128 * 36)             // 4608
#define B_OFF   (A_OFF + 2 * A_FLTS)   // 9344
#define B_STR   136
#define B_FLTS  (32 * B_STR)           // 4352
#define SMEM_FLTS (B_OFF + 2 * B_FLTS) // 18048
#define SMEM_BYTES (SMEM_FLTS * 4)     // 72192

template <bool IS_FFN1>
__device__ __forceinline__ void load_chunk(uint32_t sbase, const int* toks,
                                           int buf, int k0, int e, int m0, int n0,
                                           const float* __restrict__ Wsrc) {
    const int t = threadIdx.x;
    constexpr int NT = IS_FFN1 ? H_DIM : D_MODEL;   // B leading dim (n)
#pragma unroll
    for (int i = 0; i < 4; i++) {                   // A: 128 rows x 32 k
        int p = t + i * 256;
        int m = p >> 3, kq = p & 7;
        const float* src;
        if (IS_FFN1) src = g_xt + (size_t)toks[m] * D_MODEL + k0 + kq * 4;
        else         src = g_h + (size_t)(e * T_TOKENS + m0 + m) * H_DIM + k0 + kq * 4;
        cp_async16(sbase + (A_OFF + buf * A_FLTS + m * 36 + kq * 4) * 4, src);
    }
#pragma unroll
    for (int i = 0; i < 4; i++) {                   // B: 32 k-rows x 128 n
        int p = t + i * 256;
        int r = p >> 5, c4 = p & 31;
        const float* src = Wsrc + (size_t)(k0 + r) * NT + n0 + c4 * 4;
        cp_async16(sbase + (B_OFF + buf * B_FLTS + r * B_STR + c4 * 4) * 4, src);
    }
}

template <bool IS_FFN1>
__global__ __launch_bounds__(256)
void ffn_kernel(const float* __restrict__ bias1) {
    extern __shared__ float smem[];
    constexpr int KT = IS_FFN1 ? D_MODEL : H_DIM;
    constexpr int NC = KT / 32;

    int t = threadIdx.x, wid = t >> 5, lane = t & 31;
    int e = blockIdx.z, cnt = g_cnt[e];
    int m0 = blockIdx.x * 128;
    if (m0 >= cnt) return;
    int n0 = blockIdx.y * 128;

    int* toks = (int*)smem;                       // [128]
    if (IS_FFN1) {
        if (t < 128) {
            int m = m0 + t;
            toks[t] = (m < cnt) ? g_tok[e * T_TOKENS + m] : g_tok[e * T_TOKENS];
        }
        __syncthreads();
    }
    uint32_t sbase = smem_u32(smem);
    const float* Wsrc = (IS_FFN1 ? g_w1t : g_w2t) + (size_t)e * (D_MODEL * H_DIM);

    int g  = lane >> 2, tt = lane & 3;
    int wm = wid & 3,   wn = wid >> 2;

    float4 acc[2][8];
#pragma unroll
    for (int mt = 0; mt < 2; mt++)
#pragma unroll
        for (int nt = 0; nt < 8; nt++)
            acc[mt][nt] = make_float4(0.f, 0.f, 0.f, 0.f);

    load_chunk<IS_FFN1>(sbase, toks, 0, 0, e, m0, n0, Wsrc);
    CP_COMMIT();

    int buf = 0;
#pragma unroll 1
    for (int c = 0; c < NC; c++) {
        if (c + 1 < NC) {
            load_chunk<IS_FFN1>(sbase, toks, buf ^ 1, (c + 1) * 32, e, m0, n0, Wsrc);
            CP_COMMIT();
            CP_WAIT1();
        } else {
            CP_WAIT0();
        }
        __syncthreads();

        const float* Ab = smem + A_OFF + buf * A_FLTS + (wm * 32) * 36;
        const float* Bb = smem + B_OFF + buf * B_FLTS + wn * 64;
#pragma unroll
        for (int ks = 0; ks < 4; ks++) {
            uint32_t a[2][4];
#pragma unroll
            for (int mt = 0; mt < 2; mt++) {
                const float* Ap = Ab + mt * 16 * 36 + ks * 8;
                a[mt][0] = __float_as_uint(Ap[g * 36 + tt]);
                a[mt][1] = __float_as_uint(Ap[(g + 8) * 36 + tt]);
                a[mt][2] = __float_as_uint(Ap[g * 36 + tt + 4]);
                a[mt][3] = __float_as_uint(Ap[(g + 8) * 36 + tt + 4]);
            }
            const float* Bp = Bb + ks * 8 * B_STR;
#pragma unroll
            for (int nt = 0; nt < 8; nt++) {
                uint32_t b0 = __float_as_uint(Bp[tt * B_STR + nt * 8 + g]);
                uint32_t b1 = __float_as_uint(Bp[(tt + 4) * B_STR + nt * 8 + g]);
                mma_tf32(acc[0][nt], a[0], b0, b1);
                mma_tf32(acc[1][nt], a[1], b0, b1);
            }
        }
        __syncthreads();
        buf ^= 1;
    }

    // epilogue: c0 (g,2tt) c1 (g,2tt+1) c2 (g+8,2tt) c3 (g+8,2tt+1)
#pragma unroll
    for (int mt = 0; mt < 2; mt++) {
        int r0 = m0 + wm * 32 + mt * 16 + g;
        int r1 = r0 + 8;
#pragma unroll
        for (int nt = 0; nt < 8; nt++) {
            int col = n0 + wn * 64 + nt * 8 + 2 * tt;
            float4 d = acc[mt][nt];
            if (IS_FFN1) {
                float bx = bias1[e * H_DIM + col];
                float by = bias1[e * H_DIM + col + 1];
                if (r0 < cnt) {
                    float2 v = { to_tf32(fmaxf(d.x + bx, 0.f)),
                                 to_tf32(fmaxf(d.y + by, 0.f)) };
                    *(float2*)(g_h + (size_t)(e * T_TOKENS + r0) * H_DIM + col) = v;
                }
                if (r1 < cnt) {
                    float2 v = { to_tf32(fmaxf(d.z + bx, 0.f)),
                                 to_tf32(fmaxf(d.w + by, 0.f)) };
                    *(float2*)(g_h + (size_t)(e * T_TOKENS + r1) * H_DIM + col) = v;
                }
            } else {
                if (r0 < cnt)
                    *(float2*)(g_y + (size_t)(e * T_TOKENS + r0) * D_MODEL + col) =
                        make_float2(d.x, d.y);
                if (r1 < cnt)
                    *(float2*)(g_y + (size_t)(e * T_TOKENS + r1) * D_MODEL + col) =
                        make_float2(d.z, d.w);
            }
        }
    }
}

// ---------------- combine: out[t] = w0*(y0+b2[e0]) + w1*(y1+b2[e1]) ----------
__global__ __launch_bounds__(256)
void combine_kernel(const float* __restrict__ b2, float* __restrict__ out) {
    int i = blockIdx.x * 256 + threadIdx.x;       // per float4; T*64 total
    int tok = i >> 6, c = i & 63;
    int a0 = g_a0[tok], a1 = g_a1[tok];
    float w0 = g_wa[tok], w1 = g_wb[tok];
    const float4* y4 = (const float4*)g_y;
    const float4* b4 = (const float4*)b2;
    float4 y0 = y4[(size_t)a0 * 64 + c];
    float4 y1 = y4[(size_t)a1 * 64 + c];
    float4 v0 = b4[(a0 >> 12) * 64 + c];
    float4 v1 = b4[(a1 >> 12) * 64 + c];
    float4 o;
    o.x = w0 * (y0.x + v0.x) + w1 * (y1.x + v1.x);
    o.y = w0 * (y0.y + v0.y) + w1 * (y1.y + v1.y);
    o.z = w0 * (y0.z + v0.z) + w1 * (y1.z + v1.z);
    o.w = w0 * (y0.w + v0.w) + w1 * (y1.w + v1.w);
    ((float4*)out)[i] = o;
}

// ---------------------------------------------------------------------------
extern "C" void kernel_launch(void* const* d_in, const int* in_sizes, int n_in,
                              void* d_out, int out_size) {
    (void)in_sizes; (void)n_in; (void)out_size;
    const float* x    = (const float*)d_in[0];
    const float* Wg   = (const float*)d_in[1];
    const float* bg   = (const float*)d_in[2];
    const float* bias = (const float*)d_in[3];
    const float* W1   = (const float*)d_in[4];
    const float* b1   = (const float*)d_in[5];
    const float* W2   = (const float*)d_in[6];
    const float* b2   = (const float*)d_in[7];
    float* out = (float*)d_out;

    cudaFuncSetAttribute(ffn_kernel<true>,
                         cudaFuncAttributeMaxDynamicSharedMemorySize, SMEM_BYTES);
    cudaFuncSetAttribute(ffn_kernel<false>,
                         cudaFuncAttributeMaxDynamicSharedMemorySize, SMEM_BYTES);

    prep_kernel<<<3072, 256>>>(x, W1, W2);
    gate_kernel<<<T_TOKENS / 8, 256>>>(x, Wg, bg, bias);
    ffn_kernel<true><<<dim3(32, 4, N_EXP), 256, SMEM_BYTES>>>(b1);
    ffn_kernel<false><<<dim3(32, 2, N_EXP), 256, SMEM_BYTES>>>(nullptr);
    combine_kernel<<<T_TOKENS * 64 / 256, 256>>>(b2, out);
}